// round 6
// baseline (speedup 1.0000x reference)
#include <cuda_runtime.h>
#include <cuda_bf16.h>

// Cascaded 16-tap FIR pair == single 33-tap causal conv for columns i >= 32:
//   y[i] = x[i] + sum_{j=1}^{32} g[j] * x[i-j],  g = [1,h] (*) [1,h_rev]
// Columns [0,32) computed exactly (v-mask aware) by threads 0-3 of block x=0.
//
// Packed fma.rn.f32x2: tap pairs (g[2m+2],g[2m+1]) vs data pairs
// (x[i-2m-2],x[i-2m-1]). Window held as float2 (even pairs P free in regs);
// odd pairs Q packed per tap-chunk (2 MOV each, alu pipe). smem tile padded
// 8->12 floats per segment: conflict-free LDS.128 at the 8-float thread stride.
//
// B=256 rows, N=131072 cols, F=16.

#define F       16
#define GT      33
#define THREADS 256
#define RPT     8
#define TILE    (THREADS * RPT)    // 2048
#define HALO    32
#define NCOL    131072
#define NROW    256

#define NSEG    ((TILE + HALO) / 8)       // 260 segments of 8 floats
#define SEGP    12                         // padded segment stride (floats)

typedef unsigned long long u64;

#define FMA2(d, a, b, c) \
    asm("fma.rn.f32x2 %0, %1, %2, %3;" : "=l"(d) : "l"(a), "l"(b), "l"(c))
#define PACK2(p, lo, hi) \
    asm("mov.b64 %0, {%1, %2};" : "=l"(p) : "f"(lo), "f"(hi))
#define UNPACK2(lo, hi, p) \
    asm("mov.b64 {%0, %1}, %2;" : "=f"(lo), "=f"(hi) : "l"(p))

__global__ __launch_bounds__(THREADS, 2)
void fir2_fused(const float* __restrict__ x,
                const float* __restrict__ h,
                float* __restrict__ y)
{
    __shared__ float  sg[GT + 3];
    __shared__ float2 sgp[F];              // sgp[m] = (g[2m+2], g[2m+1])
    __shared__ float  sx[NSEG * SEGP];     // padded tile

    const int tid = threadIdx.x;
    const int row = blockIdx.y;
    const int t0  = blockIdx.x * TILE;
    const size_t rowoff = (size_t)row * NCOL;

    // ---- per-block combined taps (threads 0..32) ---------------------------
    if (tid < GT) {
        const int j = tid;
        float acc = 0.0f;
        const int a0 = (j > F) ? (j - F) : 0;
        const int a1 = (j < F) ? j : F;
        for (int a = a0; a <= a1; a++) {
            const float ka = (a == 0) ? 1.0f : __ldg(h + a - 1);
            const int bb = j - a;
            const float kb = (bb == 0) ? 1.0f : __ldg(h + F - bb);
            acc += ka * kb;
        }
        sg[j] = acc;
    }
    __syncthreads();
    if (tid < F)
        sgp[tid] = make_float2(sg[2 * tid + 2], sg[2 * tid + 1]);

    // ---- coalesced staging into padded smem --------------------------------
    // logical float k in [0, TILE+HALO) = x[row][t0 - 32 + k]
    // float4 vk -> smem float addr (vk>>1)*12 + (vk&1)*4   (16B aligned)
    {
        const float4* src = reinterpret_cast<const float4*>(x + rowoff + t0 - HALO);
        const int nvec = (TILE + HALO) / 4;          // 520
        if (blockIdx.x == 0) {
            for (int vk = tid; vk < nvec; vk += THREADS) {
                float4 v = (vk >= HALO / 4) ? src[vk] : make_float4(0.f, 0.f, 0.f, 0.f);
                *reinterpret_cast<float4*>(&sx[(vk >> 1) * SEGP + (vk & 1) * 4]) = v;
            }
        } else {
#pragma unroll
            for (int vk = tid; vk < nvec; vk += THREADS) {
                float4 v = src[vk];
                *reinterpret_cast<float4*>(&sx[(vk >> 1) * SEGP + (vk & 1) * 4]) = v;
            }
        }
    }
    __syncthreads();

    const bool edge = (blockIdx.x == 0) && (tid < 4);

    if (!edge) {
        // ---- window as float2 pairs: wp[c] = (w[2c], w[2c+1]),
        //      w[c] = x[row][t0 + tid*8 - 32 + c], c in [0,40) ---------------
        float2 wp[20];
        {
            const int k0 = tid * RPT;                // logical float base
#pragma unroll
            for (int q = 0; q < 10; q++) {
                const int k = k0 + 4 * q;
                const float4 v = *reinterpret_cast<const float4*>(
                    &sx[(k >> 3) * SEGP + (k & 7)]);
                wp[2 * q]     = make_float2(v.x, v.y);
                wp[2 * q + 1] = make_float2(v.z, v.w);
            }
        }

        u64 acc[RPT];
#pragma unroll
        for (int r = 0; r < RPT; r++) acc[r] = 0ull;

        // ---- 4 chunks of 4 tap-pairs ---------------------------------------
#pragma unroll
        for (int c = 0; c < 4; c++) {
            u64 gg[4];
#pragma unroll
            for (int mm = 0; mm < 4; mm++)
                gg[mm] = *reinterpret_cast<const u64*>(&sgp[4 * c + mm]);

            // odd-aligned pairs needed this chunk: Q[12-4c .. 18-4c]
            u64 Qb[7];
#pragma unroll
            for (int t = 0; t < 7; t++)
                PACK2(Qb[t], wp[12 - 4 * c + t].y, wp[13 - 4 * c + t].x);

#pragma unroll
            for (int r = 0; r < RPT; r++) {
                const int cb = (r >> 1) + 15;
                if ((r & 1) == 0) {
#pragma unroll
                    for (int mm = 0; mm < 4; mm++)
                        FMA2(acc[r], gg[mm],
                             *reinterpret_cast<const u64*>(&wp[cb - 4 * c - mm]),
                             acc[r]);
                } else {
#pragma unroll
                    for (int mm = 0; mm < 4; mm++)
                        FMA2(acc[r], gg[mm], Qb[(r >> 1) + 3 - mm], acc[r]);
                }
            }
        }

        // ---- finalize: identity tap + lo/hi reduce -------------------------
        float out[RPT];
#pragma unroll
        for (int r = 0; r < RPT; r++) {
            float alo, ahi;
            UNPACK2(alo, ahi, acc[r]);
            const float xi = (r & 1) ? wp[16 + (r >> 1)].y : wp[16 + (r >> 1)].x;
            out[r] = xi + alo + ahi;
        }

        float4* yo = reinterpret_cast<float4*>(y + rowoff + t0 + tid * RPT);
        yo[0] = make_float4(out[0], out[1], out[2], out[3]);
        yo[1] = make_float4(out[4], out[5], out[6], out[7]);
    } else {
        // ---- exact masked two-stage result for columns [0,32) --------------
        if (tid < 2) {
            float4* yo = reinterpret_cast<float4*>(y + rowoff + tid * RPT);
            yo[0] = make_float4(0.f, 0.f, 0.f, 0.f);   // y[0..16) = 0
            yo[1] = make_float4(0.f, 0.f, 0.f, 0.f);
        } else {
            const float* xr = x + rowoff;
            float xa[32];
#pragma unroll
            for (int c = 0; c < 32; c++) xa[c] = xr[c];
            float hh[F];
#pragma unroll
            for (int j = 0; j < F; j++) hh[j] = __ldg(h + j);

            float va[F];           // v[16..31]
#pragma unroll
            for (int t = 0; t < F; t++) {
                const int k = F + t;
                float a2 = xa[k];
#pragma unroll
                for (int j = 0; j < F; j++)
                    a2 = fmaf(hh[j], xa[k - 1 - j], a2);
                va[t] = a2;
            }
            // this thread's outputs: i in [16 + 8*(tid-2), 24 + 8*(tid-2))
            const int ib = F + RPT * (tid - 2);
            float ya[RPT];
#pragma unroll
            for (int t = 0; t < RPT; t++) {
                const int i = ib + t;
                float a2 = va[i - F];
#pragma unroll
                for (int m = 0; m < F; m++) {
                    const int k = i - F + m;      // v index; masked if < 16
                    if (k >= F) a2 = fmaf(hh[m], va[k - F], a2);
                }
                ya[t] = a2;
            }
            float4* yo = reinterpret_cast<float4*>(y + rowoff + ib);
            yo[0] = make_float4(ya[0], ya[1], ya[2], ya[3]);
            yo[1] = make_float4(ya[4], ya[5], ya[6], ya[7]);
        }
    }
}

extern "C" void kernel_launch(void* const* d_in, const int* in_sizes, int n_in,
                              void* d_out, int out_size)
{
    const float* x = (const float*)d_in[0];   // (256, 131072) f32
    const float* h = (const float*)d_in[1];   // (1, 16) f32
    float* y = (float*)d_out;                 // (256, 131072) f32

    dim3 grid(NCOL / TILE, NROW);
    fir2_fused<<<grid, THREADS>>>(x, h, y);
}

// round 7
// speedup vs baseline: 1.2567x; 1.2567x over previous
#include <cuda_runtime.h>
#include <cuda_bf16.h>

// Cascaded 16-tap FIR pair == single 33-tap causal conv for columns i >= 32:
//   y[i] = x[i] + sum_{j=1}^{32} g[j] * x[i-j],  g = [1,h] (*) [1,h_rev]
// Columns [0,32) computed exactly (v-mask aware) by threads 0-1 of block x=0.
//
// Scalar FFMA (packed f32x2 ruled out: 2x measured regression from operand
// marshalling). smem tile with 16->20 segment padding (conflict-free
// 80B-stride LDS.128). 16 outputs/thread computed as 2 groups of 8 to keep
// live regs ~58 -> 4 CTAs/SM resident.
//
// B=256 rows, N=131072 cols, F=16.

#define F       16
#define GT      33
#define THREADS 256
#define RPT     16
#define TILE    (THREADS * RPT)    // 4096
#define HALO    32
#define NCOL    131072
#define NROW    256

#define NSEG    ((TILE + HALO) / 16)      // 258 segments of 16 floats
#define SEGP    20                         // padded segment stride (floats)

__global__ __launch_bounds__(THREADS, 4)
void fir2_fused(const float* __restrict__ x,
                const float* __restrict__ h,
                float* __restrict__ y)
{
    __shared__ float sg[GT + 3];
    __shared__ float sx[NSEG * SEGP];      // padded tile

    const int tid = threadIdx.x;
    const int row = blockIdx.y;
    const int t0  = blockIdx.x * TILE;
    const size_t rowoff = (size_t)row * NCOL;

    // ---- per-block combined taps (threads 0..32) ---------------------------
    if (tid < GT) {
        const int j = tid;
        float acc = 0.0f;
        const int a0 = (j > F) ? (j - F) : 0;
        const int a1 = (j < F) ? j : F;
        for (int a = a0; a <= a1; a++) {
            const float ka = (a == 0) ? 1.0f : __ldg(h + a - 1);
            const int bb = j - a;
            const float kb = (bb == 0) ? 1.0f : __ldg(h + F - bb);
            acc += ka * kb;
        }
        sg[j] = acc;
    }

    // ---- coalesced staging into padded smem --------------------------------
    // logical float k in [0, TILE+HALO) = x[row][t0 - 32 + k]
    // float4 vk -> padded float4 slot (vk>>2)*5 + (vk&3)
    {
        const float4* src = reinterpret_cast<const float4*>(x + rowoff + t0 - HALO);
        float4* dst = reinterpret_cast<float4*>(sx);
        const int nvec = (TILE + HALO) / 4;          // 1032
        if (blockIdx.x == 0) {
            for (int vk = tid; vk < nvec; vk += THREADS) {
                float4 v = (vk >= HALO / 4) ? src[vk] : make_float4(0.f, 0.f, 0.f, 0.f);
                dst[(vk >> 2) * 5 + (vk & 3)] = v;
            }
        } else {
#pragma unroll
            for (int vk = tid; vk < nvec; vk += THREADS) {
                float4 v = src[vk];
                dst[(vk >> 2) * 5 + (vk & 3)] = v;
            }
        }
    }
    __syncthreads();

    const bool edge = (blockIdx.x == 0) && (tid < 2);

    if (!edge) {
        // ---- two groups of 8 outputs ---------------------------------------
#pragma unroll
        for (int half = 0; half < 2; half++) {
            // window: w[c] = x[row][t0 + tid*16 + 8*half - 32 + c], c in [0,40)
            // logical k = tid*16 + 8*half + c
            float w[40];
            {
                const int k0 = tid * RPT + 8 * half;
#pragma unroll
                for (int q = 0; q < 10; q++) {
                    const int k = k0 + 4 * q;
                    *reinterpret_cast<float4*>(&w[4 * q]) =
                        *reinterpret_cast<const float4*>(
                            &sx[(k >> 4) * SEGP + (k & 15)]);
                }
            }

            float acc[8];
#pragma unroll
            for (int r = 0; r < 8; r++) acc[r] = w[r + 32];   // identity tap

#pragma unroll
            for (int c = 0; c < 4; c++) {
                float t[8];
#pragma unroll
                for (int k = 0; k < 8; k++) t[k] = sg[8 * c + 1 + k];
#pragma unroll
                for (int r = 0; r < 8; r++) {
#pragma unroll
                    for (int k = 0; k < 8; k++)
                        acc[r] = fmaf(t[k], w[r + 31 - 8 * c - k], acc[r]);
                }
            }

            float4* yo = reinterpret_cast<float4*>(
                y + rowoff + t0 + tid * RPT + 8 * half);
            yo[0] = make_float4(acc[0], acc[1], acc[2], acc[3]);
            yo[1] = make_float4(acc[4], acc[5], acc[6], acc[7]);
        }
    } else {
        // ---- exact masked two-stage result for columns [0,32) --------------
        if (tid == 0) {
            float4* yo = reinterpret_cast<float4*>(y + rowoff);
#pragma unroll
            for (int q = 0; q < 4; q++)
                yo[q] = make_float4(0.f, 0.f, 0.f, 0.f);   // y[0..15] = 0
        } else {
            const float* xr = x + rowoff;
            float xa[32];
#pragma unroll
            for (int c = 0; c < 32; c++) xa[c] = xr[c];
            float hh[F];
#pragma unroll
            for (int j = 0; j < F; j++) hh[j] = __ldg(h + j);

            float va[F];           // v[16..31]
#pragma unroll
            for (int t = 0; t < F; t++) {
                const int k = F + t;
                float a2 = xa[k];
#pragma unroll
                for (int j = 0; j < F; j++)
                    a2 = fmaf(hh[j], xa[k - 1 - j], a2);
                va[t] = a2;
            }
            float ya[F];           // y[16..31]
#pragma unroll
            for (int t = 0; t < F; t++) {
                const int i = F + t;
                float a2 = va[t];
#pragma unroll
                for (int m = 0; m < F; m++) {
                    const int k = i - F + m;      // v index; masked if < 16
                    if (k >= F) a2 = fmaf(hh[m], va[k - F], a2);
                }
                ya[t] = a2;
            }
            float4* yo = reinterpret_cast<float4*>(y + rowoff + F);
#pragma unroll
            for (int q = 0; q < 4; q++)
                yo[q] = make_float4(ya[4 * q], ya[4 * q + 1],
                                    ya[4 * q + 2], ya[4 * q + 3]);
        }
    }
}

extern "C" void kernel_launch(void* const* d_in, const int* in_sizes, int n_in,
                              void* d_out, int out_size)
{
    const float* x = (const float*)d_in[0];   // (256, 131072) f32
    const float* h = (const float*)d_in[1];   // (1, 16) f32
    float* y = (float*)d_out;                 // (256, 131072) f32

    dim3 grid(NCOL / TILE, NROW);
    fir2_fused<<<grid, THREADS>>>(x, h, y);
}

// round 8
// speedup vs baseline: 1.6734x; 1.3316x over previous
#include <cuda_runtime.h>
#include <cuda_bf16.h>

// Cascaded 16-tap FIR pair == single 33-tap causal conv for columns i >= 32:
//   y[i] = x[i] + sum_{j=1}^{32} g[j] * x[i-j],  g = [1,h] (*) [1,h_rev]
// Columns [0,32) computed exactly (v-mask aware) by threads 0-1 on row-start tiles.
//
// Persistent CTAs (444 = 3/SM) + double-buffered cp.async prefetch: tile t+444
// loads into the alternate padded-smem buffer while tile t computes. Compute
// body identical to the best-known R5 structure (48-float register window,
// conflict-free 80B-stride LDS.128, 4x8 chunked taps, 32 scalar FFMA/output).
//
// B=256 rows, N=131072 cols, F=16.

#define F       16
#define GT      33
#define THREADS 256
#define RPT     16
#define TILE    (THREADS * RPT)    // 4096
#define HALO    32
#define NCOL    131072
#define NROW    256
#define TPR     (NCOL / TILE)      // 32 tiles per row
#define NTILES  (TPR * NROW)       // 8192
#define NBLK    444                // 3 per SM

#define NSEG    ((TILE + HALO) / 16)      // 258 segments of 16 floats
#define SEGP    20                         // padded segment stride (floats)
#define BUFSZ   (NSEG * SEGP)              // 5160 floats = 20640 B
#define NVEC    ((TILE + HALO) / 4)        // 1032 float4 per tile

__device__ __forceinline__ void cp16(unsigned dst, const float4* src, int sz) {
    asm volatile("cp.async.cg.shared.global [%0], [%1], 16, %2;"
                 :: "r"(dst), "l"(src), "r"(sz));
}
__device__ __forceinline__ void cp_commit() {
    asm volatile("cp.async.commit_group;");
}
template <int N> __device__ __forceinline__ void cp_wait() {
    asm volatile("cp.async.wait_group %0;" :: "n"(N));
}

__device__ __forceinline__ void stage_tile(unsigned sb, const float* x,
                                           int t, int tid)
{
    const int row = t / TPR;
    const int tir = t % TPR;
    const float4* src = reinterpret_cast<const float4*>(
        x + (size_t)row * NCOL + tir * TILE - HALO);
    const bool z = (tir == 0);
#pragma unroll
    for (int vk = tid; vk < NVEC; vk += THREADS) {
        const int sz = (z && vk < HALO / 4) ? 0 : 16;
        const float4* sp = sz ? (src + vk) : reinterpret_cast<const float4*>(x);
        cp16(sb + (((vk >> 2) * 5 + (vk & 3)) << 4), sp, sz);
    }
}

__global__ __launch_bounds__(THREADS, 3)
void fir2_fused(const float* __restrict__ x,
                const float* __restrict__ h,
                float* __restrict__ y)
{
    __shared__ float sg[GT + 3];
    __shared__ float sx[2][BUFSZ];         // double-buffered padded tiles

    const int tid = threadIdx.x;

    // ---- per-block combined taps (threads 0..32); visible after first sync --
    if (tid < GT) {
        const int j = tid;
        float acc = 0.0f;
        const int a0 = (j > F) ? (j - F) : 0;
        const int a1 = (j < F) ? j : F;
        for (int a = a0; a <= a1; a++) {
            const float ka = (a == 0) ? 1.0f : __ldg(h + a - 1);
            const int bb = j - a;
            const float kb = (bb == 0) ? 1.0f : __ldg(h + F - bb);
            acc += ka * kb;
        }
        sg[j] = acc;
    }

    unsigned sbase[2];
    sbase[0] = (unsigned)__cvta_generic_to_shared(&sx[0][0]);
    sbase[1] = (unsigned)__cvta_generic_to_shared(&sx[1][0]);

    // ---- prefetch first tile ------------------------------------------------
    int t = blockIdx.x;
    stage_tile(sbase[0], x, t, tid);
    cp_commit();

    int buf = 0;
    for (; t < NTILES; t += NBLK, buf ^= 1) {
        // prefetch next tile into the other buffer
        const int tn = t + NBLK;
        if (tn < NTILES) stage_tile(sbase[buf ^ 1], x, tn, tid);
        cp_commit();
        cp_wait<1>();                      // current tile's group complete
        __syncthreads();

        const int row = t / TPR;
        const int tir = t % TPR;
        const int t0  = tir * TILE;
        const size_t rowoff = (size_t)row * NCOL;
        const float* sxc = sx[buf];

        if (!(tir == 0 && tid < 2)) {
            // window: w[c] = x[row][t0 + tid*16 - 32 + c], c in [0,48)
            float w[RPT + HALO];
            {
                const int k0 = tid * RPT;
#pragma unroll
                for (int q = 0; q < 12; q++) {
                    const int k = k0 + 4 * q;
                    *reinterpret_cast<float4*>(&w[4 * q]) =
                        *reinterpret_cast<const float4*>(
                            &sxc[(k >> 4) * SEGP + (k & 15)]);
                }
            }

            float acc[RPT];
#pragma unroll
            for (int r = 0; r < RPT; r++) acc[r] = w[r + 32];   // identity tap

#pragma unroll
            for (int c = 0; c < 4; c++) {
                float tp[8];
#pragma unroll
                for (int k = 0; k < 8; k++) tp[k] = sg[8 * c + 1 + k];
#pragma unroll
                for (int r = 0; r < RPT; r++) {
#pragma unroll
                    for (int k = 0; k < 8; k++)
                        acc[r] = fmaf(tp[k], w[r + 31 - 8 * c - k], acc[r]);
                }
            }

            float4* yo = reinterpret_cast<float4*>(y + rowoff + t0 + tid * RPT);
#pragma unroll
            for (int q = 0; q < 4; q++)
                yo[q] = make_float4(acc[4 * q], acc[4 * q + 1],
                                    acc[4 * q + 2], acc[4 * q + 3]);
        } else {
            // ---- exact masked two-stage result for columns [0,32) ----------
            if (tid == 0) {
                float4* yo = reinterpret_cast<float4*>(y + rowoff);
#pragma unroll
                for (int q = 0; q < 4; q++)
                    yo[q] = make_float4(0.f, 0.f, 0.f, 0.f);   // y[0..15] = 0
            } else {
                const float* xr = x + rowoff;
                float xa[32];
#pragma unroll
                for (int c = 0; c < 32; c++) xa[c] = xr[c];
                float hh[F];
#pragma unroll
                for (int j = 0; j < F; j++) hh[j] = __ldg(h + j);

                float va[F];           // v[16..31]
#pragma unroll
                for (int tt = 0; tt < F; tt++) {
                    const int k = F + tt;
                    float a2 = xa[k];
#pragma unroll
                    for (int j = 0; j < F; j++)
                        a2 = fmaf(hh[j], xa[k - 1 - j], a2);
                    va[tt] = a2;
                }
                float ya[F];           // y[16..31]
#pragma unroll
                for (int tt = 0; tt < F; tt++) {
                    const int i = F + tt;
                    float a2 = va[tt];
#pragma unroll
                    for (int m = 0; m < F; m++) {
                        const int k = i - F + m;   // v index; masked if < 16
                        if (k >= F) a2 = fmaf(hh[m], va[k - F], a2);
                    }
                    ya[tt] = a2;
                }
                float4* yo = reinterpret_cast<float4*>(y + rowoff + F);
#pragma unroll
                for (int q = 0; q < 4; q++)
                    yo[q] = make_float4(ya[4 * q], ya[4 * q + 1],
                                        ya[4 * q + 2], ya[4 * q + 3]);
            }
        }
        __syncthreads();               // all reads of sx[buf] done before it is
                                       // overwritten by the prefetch 2 iters on
    }
}

extern "C" void kernel_launch(void* const* d_in, const int* in_sizes, int n_in,
                              void* d_out, int out_size)
{
    const float* x = (const float*)d_in[0];   // (256, 131072) f32
    const float* h = (const float*)d_in[1];   // (1, 16) f32
    float* y = (float*)d_out;                 // (256, 131072) f32

    fir2_fused<<<NBLK, THREADS>>>(x, h, y);
}

// round 9
// speedup vs baseline: 1.6763x; 1.0017x over previous
#include <cuda_runtime.h>
#include <cuda_bf16.h>

// Cascaded 16-tap FIR pair == single 33-tap causal conv for columns i >= 32:
//   y[i] = x[i] + sum_{j=1}^{32} g[j] * x[i-j],  g = [1,h] (*) [1,h_rev]
// Columns [0,32) computed exactly (v-mask aware) by threads 0-1 on row-start tiles.
//
// Persistent CTAs (592 = 4/SM) + double-buffered cp.async prefetch. Compute
// body: 48-float register window (conflict-free 80B-stride LDS.128 from the
// 16->20 padded tile), 4x8 chunked taps loaded as 2x LDS.128 per chunk,
// 32 scalar FFMA/output (minimum).
//
// B=256 rows, N=131072 cols, F=16.

#define F       16
#define GT      33
#define THREADS 256
#define RPT     16
#define TILE    (THREADS * RPT)    // 4096
#define HALO    32
#define NCOL    131072
#define NROW    256
#define TPR     (NCOL / TILE)      // 32 tiles per row
#define NTILES  (TPR * NROW)       // 8192
#define NBLK    592                // 4 per SM

#define NSEG    ((TILE + HALO) / 16)      // 258 segments of 16 floats
#define SEGP    20                         // padded segment stride (floats)
#define BUFSZ   (NSEG * SEGP)              // 5160 floats = 20640 B
#define NVEC    ((TILE + HALO) / 4)        // 1032 float4 per tile

__device__ __forceinline__ void cp16(unsigned dst, const float4* src, int sz) {
    asm volatile("cp.async.cg.shared.global [%0], [%1], 16, %2;"
                 :: "r"(dst), "l"(src), "r"(sz));
}
__device__ __forceinline__ void cp_commit() {
    asm volatile("cp.async.commit_group;");
}
template <int N> __device__ __forceinline__ void cp_wait() {
    asm volatile("cp.async.wait_group %0;" :: "n"(N));
}

__device__ __forceinline__ void stage_tile(unsigned sb, const float* x,
                                           int t, int tid)
{
    const int row = t / TPR;
    const int tir = t % TPR;
    const float4* src = reinterpret_cast<const float4*>(
        x + (size_t)row * NCOL + tir * TILE - HALO);
    const bool z = (tir == 0);
#pragma unroll
    for (int vk = tid; vk < NVEC; vk += THREADS) {
        const int sz = (z && vk < HALO / 4) ? 0 : 16;
        const float4* sp = sz ? (src + vk) : reinterpret_cast<const float4*>(x);
        cp16(sb + (((vk >> 2) * 5 + (vk & 3)) << 4), sp, sz);
    }
}

__global__ __launch_bounds__(THREADS, 4)
void fir2_fused(const float* __restrict__ x,
                const float* __restrict__ h,
                float* __restrict__ y)
{
    __shared__ float  sg[GT + 3];
    __shared__ float4 sgc[8];              // taps g[1..32] repacked, 16B aligned
    __shared__ float  sx[2][BUFSZ];        // double-buffered padded tiles

    const int tid = threadIdx.x;

    // ---- per-block combined taps (threads 0..32) ----------------------------
    if (tid < GT) {
        const int j = tid;
        float acc = 0.0f;
        const int a0 = (j > F) ? (j - F) : 0;
        const int a1 = (j < F) ? j : F;
        for (int a = a0; a <= a1; a++) {
            const float ka = (a == 0) ? 1.0f : __ldg(h + a - 1);
            const int bb = j - a;
            const float kb = (bb == 0) ? 1.0f : __ldg(h + F - bb);
            acc += ka * kb;
        }
        sg[j] = acc;
    }

    unsigned sbase[2];
    sbase[0] = (unsigned)__cvta_generic_to_shared(&sx[0][0]);
    sbase[1] = (unsigned)__cvta_generic_to_shared(&sx[1][0]);

    // ---- prefetch first tile ------------------------------------------------
    int t = blockIdx.x;
    stage_tile(sbase[0], x, t, tid);
    cp_commit();
    __syncthreads();                       // sg ready

    // repack taps for LDS.128 access: ((float*)sgc)[k] = g[k+1], k in [0,32)
    if (tid < 32) reinterpret_cast<float*>(sgc)[tid] = sg[tid + 1];
    // (visibility to all threads via the in-loop __syncthreads before compute)

    int buf = 0;
    for (; t < NTILES; t += NBLK, buf ^= 1) {
        // prefetch next tile into the other buffer
        const int tn = t + NBLK;
        if (tn < NTILES) stage_tile(sbase[buf ^ 1], x, tn, tid);
        cp_commit();
        cp_wait<1>();                      // current tile's group complete
        __syncthreads();

        const int row = t / TPR;
        const int tir = t % TPR;
        const int t0  = tir * TILE;
        const size_t rowoff = (size_t)row * NCOL;
        const float* sxc = sx[buf];

        if (!(tir == 0 && tid < 2)) {
            // window: w[c] = x[row][t0 + tid*16 - 32 + c], c in [0,48)
            float w[RPT + HALO];
            {
                const int k0 = tid * RPT;
#pragma unroll
                for (int q = 0; q < 12; q++) {
                    const int k = k0 + 4 * q;
                    *reinterpret_cast<float4*>(&w[4 * q]) =
                        *reinterpret_cast<const float4*>(
                            &sxc[(k >> 4) * SEGP + (k & 15)]);
                }
            }

            float acc[RPT];
#pragma unroll
            for (int r = 0; r < RPT; r++) acc[r] = w[r + 32];   // identity tap

#pragma unroll
            for (int c = 0; c < 4; c++) {
                float tp[8];
                *reinterpret_cast<float4*>(&tp[0]) = sgc[2 * c];
                *reinterpret_cast<float4*>(&tp[4]) = sgc[2 * c + 1];
#pragma unroll
                for (int r = 0; r < RPT; r++) {
#pragma unroll
                    for (int k = 0; k < 8; k++)
                        acc[r] = fmaf(tp[k], w[r + 31 - 8 * c - k], acc[r]);
                }
            }

            float4* yo = reinterpret_cast<float4*>(y + rowoff + t0 + tid * RPT);
#pragma unroll
            for (int q = 0; q < 4; q++)
                yo[q] = make_float4(acc[4 * q], acc[4 * q + 1],
                                    acc[4 * q + 2], acc[4 * q + 3]);
        } else {
            // ---- exact masked two-stage result for columns [0,32) ----------
            if (tid == 0) {
                float4* yo = reinterpret_cast<float4*>(y + rowoff);
#pragma unroll
                for (int q = 0; q < 4; q++)
                    yo[q] = make_float4(0.f, 0.f, 0.f, 0.f);   // y[0..15] = 0
            } else {
                const float* xr = x + rowoff;
                float xa[32];
#pragma unroll
                for (int c = 0; c < 32; c++) xa[c] = xr[c];
                float hh[F];
#pragma unroll
                for (int j = 0; j < F; j++) hh[j] = __ldg(h + j);

                float va[F];           // v[16..31]
#pragma unroll
                for (int tt = 0; tt < F; tt++) {
                    const int k = F + tt;
                    float a2 = xa[k];
#pragma unroll
                    for (int j = 0; j < F; j++)
                        a2 = fmaf(hh[j], xa[k - 1 - j], a2);
                    va[tt] = a2;
                }
                float ya[F];           // y[16..31]
#pragma unroll
                for (int tt = 0; tt < F; tt++) {
                    const int i = F + tt;
                    float a2 = va[tt];
#pragma unroll
                    for (int m = 0; m < F; m++) {
                        const int k = i - F + m;   // v index; masked if < 16
                        if (k >= F) a2 = fmaf(hh[m], va[k - F], a2);
                    }
                    ya[tt] = a2;
                }
                float4* yo = reinterpret_cast<float4*>(y + rowoff + F);
#pragma unroll
                for (int q = 0; q < 4; q++)
                    yo[q] = make_float4(ya[4 * q], ya[4 * q + 1],
                                        ya[4 * q + 2], ya[4 * q + 3]);
            }
        }
        __syncthreads();               // protect sx[buf^1] (being prefetched)
                                       // and sgc on the first iteration
    }
}

extern "C" void kernel_launch(void* const* d_in, const int* in_sizes, int n_in,
                              void* d_out, int out_size)
{
    const float* x = (const float*)d_in[0];   // (256, 131072) f32
    const float* h = (const float*)d_in[1];   // (1, 16) f32
    float* y = (float*)d_out;                 // (256, 131072) f32

    fir2_fused<<<NBLK, THREADS>>>(x, h, y);
}